// round 3
// baseline (speedup 1.0000x reference)
#include <cuda_runtime.h>
#include <math.h>
#include <stdint.h>

#define BB   2048
#define NN   64
#define DD   512
#define HH   8
#define HDIM 64
#define LL   3
#define FFD  2048
#define EE   100000
#define RR   400
#define MROWS (BB*NN)   // 131072

// ---------------- scratch (allocation-free: __device__ globals) ----------------
__device__ float g_h   [BB*DD];
__device__ float g_q   [BB*DD];
__device__ float g_hc  [BB*DD];
__device__ float g_qh  [BB*DD];
__device__ float g_x   [BB*DD];
__device__ float g_ff  [BB*FFD];
__device__ float g_mix [BB*HH*DD];      // [B][h*512+d] = 2048 x 4096
__device__ float g_val [MROWS*DD];      // 268 MB
__device__ float g_ec  [EE*DD];         // 205 MB
__device__ float g_rc  [RR*DD];
__device__ float g_khR [LL*RR*DD];      // [l][r][h*64+e]
__device__ float g_wt  [2*LL*DD*DD];    // transposed Wq,Wk -> [(type*LL+l)][d][h*64+e]
__device__ float g_wvb [LL*HH*DD*HDIM*HH]; // block-diag Wv: [l][4096][512]
__device__ float g_zero[DD];            // static zero bias (never written)

// ---------------- helpers ----------------
__device__ __forceinline__ float to_tf32(float x) {
    uint32_t u;
    asm("cvt.rna.tf32.f32 %0, %1;" : "=r"(u) : "f"(x));
    return __uint_as_float(u);
}

__device__ __forceinline__ void mma_tf32(float c[4], const float a[4], const float b[2]) {
    uint32_t a0 = __float_as_uint(a[0]), a1 = __float_as_uint(a[1]);
    uint32_t a2 = __float_as_uint(a[2]), a3 = __float_as_uint(a[3]);
    uint32_t b0 = __float_as_uint(b[0]), b1 = __float_as_uint(b[1]);
    asm volatile(
        "mma.sync.aligned.m16n8k8.row.col.f32.tf32.tf32.f32 "
        "{%0,%1,%2,%3}, {%4,%5,%6,%7}, {%8,%9}, {%0,%1,%2,%3};\n"
        : "+f"(c[0]), "+f"(c[1]), "+f"(c[2]), "+f"(c[3])
        : "r"(a0), "r"(a1), "r"(a2), "r"(a3), "r"(b0), "r"(b1));
}

// ---------------- weight prep ----------------
// transpose Wq,Wk: W[l,h,d,e] -> wt[(type*LL+l)][d][h*64+e]
__global__ void prep_w_k(const float* __restrict__ Wq, const float* __restrict__ Wk,
                         float* __restrict__ wt) {
    int idx = blockIdx.x * blockDim.x + threadIdx.x;   // 2*LL*DD*DD
    int j    = idx & 511;
    int rest = idx >> 9;
    int d    = rest & 511;
    rest   >>= 9;
    int l    = rest % LL;
    int type = rest / LL;
    const float* W = (type == 0) ? Wq : Wk;
    int hh = j >> 6, e = j & 63;
    wt[idx] = W[(((size_t)l * HH + hh) * DD + d) * HDIM + e];
}

// block-diagonal Wv: wvb[l][h*512+d][h*64+e] = Wv[l,h,d,e], else 0
__global__ void prep_wvb_k(const float* __restrict__ Wv, float* __restrict__ wvb) {
    int idx = blockIdx.x * blockDim.x + threadIdx.x;  // LL*4096*512
    int j    = idx & 511;
    int rest = idx >> 9;
    int row  = rest & 4095;
    int l    = rest >> 12;
    int hr = row >> 9, d = row & 511;
    int hj = j >> 6,  e = j & 63;
    float v = 0.f;
    if (hr == hj) v = Wv[(((size_t)l * HH + hr) * DD + d) * HDIM + e];
    wvb[idx] = v;
}

// ---------------- gathers ----------------
__global__ void gather_hq_k(const int* __restrict__ e1, const int* __restrict__ qi,
                            const float* __restrict__ emb_e, const float* __restrict__ emb_r,
                            float* __restrict__ h, float* __restrict__ q,
                            float* __restrict__ out, int writeQ) {
    int idx = blockIdx.x * blockDim.x + threadIdx.x;   // BB*DD
    int b = idx >> 9, d = idx & 511;
    h[idx] = emb_e[(size_t)e1[b] * DD + d];
    float qv = emb_r[(size_t)qi[b] * DD + d];
    q[idx] = qv;
    if (writeQ) out[BB * DD + idx] = qv;
}

// ---------------- small GEMM: 4 rows per block, N=K=512 ----------------
// C[r][j] = sum_k A[r][k]*B[k][j] (+bias[j] if bias != null)
__global__ void small4_mm_k(const float* __restrict__ A, const float* __restrict__ B,
                            const float* __restrict__ bias, float* __restrict__ C) {
    __shared__ float As[4][512];
    int tid = threadIdx.x;
    int r0 = blockIdx.x * 4;
    for (int i = tid; i < 4 * 512; i += 256)
        As[i >> 9][i & 511] = A[(size_t)(r0 + (i >> 9)) * 512 + (i & 511)];
    __syncthreads();
    int j0 = tid, j1 = tid + 256;
    float acc[4][2] = {};
    for (int k = 0; k < 512; k++) {
        float b0 = B[(size_t)k * 512 + j0];
        float b1 = B[(size_t)k * 512 + j1];
        #pragma unroll
        for (int r = 0; r < 4; r++) {
            acc[r][0] += As[r][k] * b0;
            acc[r][1] += As[r][k] * b1;
        }
    }
    float bb0 = bias ? bias[j0] : 0.f;
    float bb1 = bias ? bias[j1] : 0.f;
    #pragma unroll
    for (int r = 0; r < 4; r++) {
        C[(size_t)(r0 + r) * 512 + j0] = acc[r][0] + bb0;
        C[(size_t)(r0 + r) * 512 + j1] = acc[r][1] + bb1;
    }
}

// ---------------- TF32 split tensor-core GEMM ----------------
// C[M,Ncol] = act(A @ B + bias). BM=BN=128, BK=32, 256 threads, 8 warps (2x4).
// x = hi + lo tf32 split; accumulate hi*hi + hi*lo + lo*hi.
// M may be non-multiple of 128 (loads clamped, stores guarded).
// EPI 0: none, 1: relu
#define SLABF 4224          // 32 * 132 floats per smem array per stage
#define TG_SMEM (2 * 4 * SLABF * 4)   // 135168 bytes

template<int EPI>
__global__ void __launch_bounds__(256, 1)
tgemm_k(const float* __restrict__ A, const float* __restrict__ Bm,
        const float* __restrict__ bias, float* __restrict__ C,
        int M, int Ncol, int K) {
    extern __shared__ float smem[];
    int tid  = threadIdx.x;
    int lane = tid & 31, wid = tid >> 5;
    int warp_m = wid & 1, warp_n = wid >> 1;   // 2 (m) x 4 (n)
    int g = lane >> 2, t4 = lane & 3;
    int bm = blockIdx.y * 128, bn = blockIdx.x * 128;

    int a_kq = tid & 7, a_r0 = tid >> 3;   // A loader: k-quad, row base
    int b_n4 = tid & 31, b_k0 = tid >> 5;  // B loader: n4, k row

    float c[4][4][4];
    #pragma unroll
    for (int i = 0; i < 4; i++)
        #pragma unroll
        for (int j = 0; j < 4; j++)
            #pragma unroll
            for (int r = 0; r < 4; r++) c[i][j][r] = 0.f;

    float4 regA[4], regB[4];

    auto loadG = [&](int k0) {
        int k = k0 + a_kq * 4;
        #pragma unroll
        for (int i = 0; i < 4; i++) {
            int row = bm + a_r0 + i * 32;
            if (row >= M) row = M - 1;
            regA[i] = *(const float4*)(A + (size_t)row * K + k);
        }
        #pragma unroll
        for (int i = 0; i < 4; i++) {
            int kr = k0 + b_k0 + i * 8;
            regB[i] = *(const float4*)(Bm + (size_t)kr * Ncol + bn + b_n4 * 4);
        }
    };

    auto storeS = [&](int st) {
        float* aH = smem + st * 4 * SLABF;
        float* aL = aH + SLABF;
        float* bH = aH + 2 * SLABF;
        float* bL = aH + 3 * SLABF;
        #pragma unroll
        for (int i = 0; i < 4; i++) {
            float v[4] = {regA[i].x, regA[i].y, regA[i].z, regA[i].w};
            #pragma unroll
            for (int j = 0; j < 4; j++) {
                float hi = to_tf32(v[j]);
                float lo = to_tf32(v[j] - hi);
                int off = (a_kq * 4 + j) * 132 + a_r0 + i * 32;
                aH[off] = hi;
                aL[off] = lo;
            }
        }
        #pragma unroll
        for (int i = 0; i < 4; i++) {
            float v[4] = {regB[i].x, regB[i].y, regB[i].z, regB[i].w};
            float h0 = to_tf32(v[0]), h1 = to_tf32(v[1]);
            float h2 = to_tf32(v[2]), h3 = to_tf32(v[3]);
            float4 hv = make_float4(h0, h1, h2, h3);
            float4 lv = make_float4(to_tf32(v[0] - h0), to_tf32(v[1] - h1),
                                    to_tf32(v[2] - h2), to_tf32(v[3] - h3));
            int off = (b_k0 + i * 8) * 132 + b_n4 * 4;
            *(float4*)&bH[off] = hv;
            *(float4*)&bL[off] = lv;
        }
    };

    auto compute = [&](int st) {
        float* aH = smem + st * 4 * SLABF;
        float* aL = aH + SLABF;
        float* bH = aH + 2 * SLABF;
        float* bL = aH + 3 * SLABF;
        #pragma unroll
        for (int ks = 0; ks < 4; ks++) {
            int kb = ks * 8;
            float ah[4][4], al[4][4];
            #pragma unroll
            for (int mt = 0; mt < 4; mt++) {
                int rm = warp_m * 64 + mt * 16 + g;
                int o0 = (kb + t4) * 132 + rm;
                int o1 = (kb + t4 + 4) * 132 + rm;
                ah[mt][0] = aH[o0];     ah[mt][1] = aH[o0 + 8];
                ah[mt][2] = aH[o1];     ah[mt][3] = aH[o1 + 8];
                al[mt][0] = aL[o0];     al[mt][1] = aL[o0 + 8];
                al[mt][2] = aL[o1];     al[mt][3] = aL[o1 + 8];
            }
            float bh[4][2], bl[4][2];
            #pragma unroll
            for (int nt = 0; nt < 4; nt++) {
                int cn = warp_n * 32 + nt * 8 + g;
                bh[nt][0] = bH[(kb + t4) * 132 + cn];
                bh[nt][1] = bH[(kb + t4 + 4) * 132 + cn];
                bl[nt][0] = bL[(kb + t4) * 132 + cn];
                bl[nt][1] = bL[(kb + t4 + 4) * 132 + cn];
            }
            #pragma unroll
            for (int mt = 0; mt < 4; mt++)
                #pragma unroll
                for (int nt = 0; nt < 4; nt++) {
                    mma_tf32(c[mt][nt], ah[mt], bh[nt]);
                    mma_tf32(c[mt][nt], ah[mt], bl[nt]);
                    mma_tf32(c[mt][nt], al[mt], bh[nt]);
                }
        }
    };

    int nslab = K >> 5;
    loadG(0);
    storeS(0);
    __syncthreads();
    int cur = 0;
    for (int s = 0; s < nslab; s++) {
        if (s + 1 < nslab) loadG((s + 1) * 32);
        compute(cur);
        if (s + 1 < nslab) storeS(cur ^ 1);
        __syncthreads();
        cur ^= 1;
    }

    #pragma unroll
    for (int mt = 0; mt < 4; mt++) {
        int r0 = bm + warp_m * 64 + mt * 16 + g;
        #pragma unroll
        for (int nt = 0; nt < 4; nt++) {
            int cc = bn + warp_n * 32 + nt * 8 + 2 * t4;
            float bi0 = bias[cc], bi1 = bias[cc + 1];
            float v0 = c[mt][nt][0] + bi0, v1 = c[mt][nt][1] + bi1;
            float v2 = c[mt][nt][2] + bi0, v3 = c[mt][nt][3] + bi1;
            if (EPI == 1) {
                v0 = fmaxf(v0, 0.f); v1 = fmaxf(v1, 0.f);
                v2 = fmaxf(v2, 0.f); v3 = fmaxf(v3, 0.f);
            }
            if (r0 < M)
                *(float2*)(C + (size_t)r0 * Ncol + cc) = make_float2(v0, v1);
            if (r0 + 8 < M)
                *(float2*)(C + (size_t)(r0 + 8) * Ncol + cc) = make_float2(v2, v3);
        }
    }
}

// ---------------- value build: leaky(hc[b] + rc[nbr_r] + ec[nbr_e]) ----------------
__global__ void value_build_k(const float4* __restrict__ hc, const float4* __restrict__ rc,
                              const float4* __restrict__ ec, const int* __restrict__ nr,
                              const int* __restrict__ ne, float4* __restrict__ val) {
    size_t idx = (size_t)blockIdx.x * blockDim.x + threadIdx.x;  // MROWS*128
    size_t row = idx >> 7;
    int d4 = (int)(idx & 127);
    int b = (int)(row >> 6);
    int ir = nr[row], ie = ne[row];
    float4 a = hc[(size_t)b * 128 + d4];
    float4 r = rc[(size_t)ir * 128 + d4];
    float4 e = ec[(size_t)ie * 128 + d4];
    float4 v;
    v.x = a.x + r.x + e.x; v.y = a.y + r.y + e.y;
    v.z = a.z + r.z + e.z; v.w = a.w + r.w + e.w;
    v.x = (v.x > 0.f) ? v.x : 0.01f * v.x;
    v.y = (v.y > 0.f) ? v.y : 0.01f * v.y;
    v.z = (v.z > 0.f) ? v.z : 0.01f * v.z;
    v.w = (v.w > 0.f) ? v.w : 0.01f * v.w;
    val[idx] = v;
}

// ---------------- fused attention: scores + softmax + attn@value -> mix ----------------
// one block per batch b, 256 threads (8 warps, warp = head)
__global__ void __launch_bounds__(256)
attn_fused_k(const float* __restrict__ qh, const float* __restrict__ khR,
             const int* __restrict__ nr, const float* __restrict__ masks,
             const float* __restrict__ val, float* __restrict__ mix) {
    __shared__ float qs[512];
    __shared__ float attn_s[8][64];
    __shared__ int   nbr_s[64];
    __shared__ float msk_s[64];
    __shared__ float vs[16][516];
    int b = blockIdx.x, tid = threadIdx.x;
    int lane = tid & 31, h = tid >> 5;

    qs[tid]       = qh[(size_t)b * 512 + tid];
    qs[tid + 256] = qh[(size_t)b * 512 + tid + 256];
    if (tid < 64) {
        nbr_s[tid] = nr[b * 64 + tid];
        msk_s[tid] = masks[b * 64 + tid];
    }
    __syncthreads();

    // scores: each lane handles n = lane and n = lane+32 for head h
    float sc[2];
    #pragma unroll
    for (int half = 0; half < 2; half++) {
        int n = lane + 32 * half;
        const float4* kr = (const float4*)(khR + (size_t)nbr_s[n] * 512 + h * 64);
        float v = 0.f;
        #pragma unroll
        for (int i = 0; i < 16; i++) {
            float4 k4 = kr[i];
            v += qs[h * 64 + 4 * i]     * k4.x;
            v += qs[h * 64 + 4 * i + 1] * k4.y;
            v += qs[h * 64 + 4 * i + 2] * k4.z;
            v += qs[h * 64 + 4 * i + 3] * k4.w;
        }
        sc[half] = v * 0.125f - 1e31f * (1.f - msk_s[n]);
    }
    // softmax over 64 scores within the warp
    float mx = fmaxf(sc[0], sc[1]);
    #pragma unroll
    for (int o = 16; o; o >>= 1) mx = fmaxf(mx, __shfl_xor_sync(0xffffffffu, mx, o));
    float e0 = expf(sc[0] - mx), e1 = expf(sc[1] - mx);
    float sm = e0 + e1;
    #pragma unroll
    for (int o = 16; o; o >>= 1) sm += __shfl_xor_sync(0xffffffffu, sm, o);
    float inv = 1.f / sm;
    attn_s[h][lane]      = e0 * inv;
    attn_s[h][lane + 32] = e1 * inv;
    // no cross-warp dependency on attn_s: each warp reads only its own row

    // mix[h][d] = sum_n attn[h][n] * value[b][n][d], d split across lanes
    float acc[16];
    #pragma unroll
    for (int i = 0; i < 16; i++) acc[i] = 0.f;

    int rr = tid >> 4, cc = tid & 15;
    for (int c = 0; c < 4; c++) {
        __syncthreads();
        const float4* src = (const float4*)(val + ((size_t)b * 64 + c * 16) * 512);
        #pragma unroll
        for (int i = 0; i < 8; i++) {
            float4 vv = src[(size_t)rr * 128 + cc + i * 16];
            *(float4*)&vs[rr][(cc + i * 16) * 4] = vv;
        }
        __syncthreads();
        #pragma unroll
        for (int n = 0; n < 16; n++) {
            float a = attn_s[h][c * 16 + n];
            #pragma unroll
            for (int i = 0; i < 16; i++) acc[i] += a * vs[n][lane + 32 * i];
        }
    }

    float* mo = mix + (size_t)b * 4096 + h * 512;
    #pragma unroll
    for (int i = 0; i < 16; i++) mo[lane + 32 * i] = acc[i];
}

// ---------------- residual add + layernorm (biased var, eps=1e-5) ----------------
__global__ void addln_k(float* __restrict__ h, const float* __restrict__ x,
                        const float* __restrict__ g, const float* __restrict__ be) {
    __shared__ float red[8];
    int b = blockIdx.x, t = threadIdx.x;  // 256
    size_t base = (size_t)b * DD;
    float v0 = h[base + t]       + x[base + t];
    float v1 = h[base + t + 256] + x[base + t + 256];
    float s = v0 + v1;
    #pragma unroll
    for (int o = 16; o; o >>= 1) s += __shfl_xor_sync(0xffffffffu, s, o);
    if ((t & 31) == 0) red[t >> 5] = s;
    __syncthreads();
    float mean = 0.f;
    #pragma unroll
    for (int i = 0; i < 8; i++) mean += red[i];
    mean *= (1.0f / DD);
    __syncthreads();
    float d0 = v0 - mean, d1 = v1 - mean;
    float vs = d0 * d0 + d1 * d1;
    #pragma unroll
    for (int o = 16; o; o >>= 1) vs += __shfl_xor_sync(0xffffffffu, vs, o);
    if ((t & 31) == 0) red[t >> 5] = vs;
    __syncthreads();
    float var = 0.f;
    #pragma unroll
    for (int i = 0; i < 8; i++) var += red[i];
    var *= (1.0f / DD);
    float inv = rsqrtf(var + 1e-5f);
    h[base + t]       = d0 * inv * g[t]       + be[t];
    h[base + t + 256] = d1 * inv * g[t + 256] + be[t + 256];
}

__global__ void out_copy_k(const float* __restrict__ h, float* __restrict__ out) {
    int idx = blockIdx.x * blockDim.x + threadIdx.x;
    out[idx] = h[idx];
}

// ---------------- launch ----------------
extern "C" void kernel_launch(void* const* d_in, const int* in_sizes, int n_in,
                              void* d_out, int out_size) {
    const int*   e1    = (const int*)  d_in[0];
    const int*   qi    = (const int*)  d_in[1];
    const int*   nr    = (const int*)  d_in[2];
    const int*   ne    = (const int*)  d_in[3];
    const float* masks = (const float*)d_in[4];
    const float* emb_e = (const float*)d_in[5];
    const float* emb_r = (const float*)d_in[6];
    const float* msgW  = (const float*)d_in[7];
    const float* msgb  = (const float*)d_in[8];
    const float* Wq    = (const float*)d_in[9];
    const float* bq    = (const float*)d_in[10];
    const float* Wk    = (const float*)d_in[11];
    const float* bk    = (const float*)d_in[12];
    const float* Wv    = (const float*)d_in[13];
    const float* bv    = (const float*)d_in[14];
    const float* fW1   = (const float*)d_in[15];
    const float* fb1   = (const float*)d_in[16];
    const float* fW2   = (const float*)d_in[17];
    const float* fb2   = (const float*)d_in[18];
    const float* l1g   = (const float*)d_in[19];
    const float* l1b   = (const float*)d_in[20];
    const float* l2g   = (const float*)d_in[21];
    const float* l2b   = (const float*)d_in[22];
    float* out = (float*)d_out;

    float *p_h, *p_q, *p_hc, *p_qh, *p_x, *p_ff, *p_mix, *p_val, *p_ec, *p_rc, *p_khR,
          *p_wt, *p_wvb, *p_zero;
    cudaGetSymbolAddress((void**)&p_h,   g_h);
    cudaGetSymbolAddress((void**)&p_q,   g_q);
    cudaGetSymbolAddress((void**)&p_hc,  g_hc);
    cudaGetSymbolAddress((void**)&p_qh,  g_qh);
    cudaGetSymbolAddress((void**)&p_x,   g_x);
    cudaGetSymbolAddress((void**)&p_ff,  g_ff);
    cudaGetSymbolAddress((void**)&p_mix, g_mix);
    cudaGetSymbolAddress((void**)&p_val, g_val);
    cudaGetSymbolAddress((void**)&p_ec,  g_ec);
    cudaGetSymbolAddress((void**)&p_rc,  g_rc);
    cudaGetSymbolAddress((void**)&p_khR, g_khR);
    cudaGetSymbolAddress((void**)&p_wt,  g_wt);
    cudaGetSymbolAddress((void**)&p_wvb, g_wvb);
    cudaGetSymbolAddress((void**)&p_zero,g_zero);

    cudaFuncSetAttribute(tgemm_k<0>, cudaFuncAttributeMaxDynamicSharedMemorySize, TG_SMEM);
    cudaFuncSetAttribute(tgemm_k<1>, cudaFuncAttributeMaxDynamicSharedMemorySize, TG_SMEM);

    int writeQ = (out_size >= 2 * BB * DD) ? 1 : 0;

    // ---- prep ----
    prep_w_k<<<(2 * LL * DD * DD) / 256, 256>>>(Wq, Wk, p_wt);
    prep_wvb_k<<<(LL * 4096 * 512) / 256, 256>>>(Wv, p_wvb);
    gather_hq_k<<<(BB * DD) / 256, 256>>>(e1, qi, emb_e, emb_r, p_h, p_q, out, writeQ);

    // rc = emb_r @ W_r  (no bias)
    small4_mm_k<<<RR / 4, 256>>>(emb_r, msgW + (size_t)DD * DD, nullptr, p_rc);
    // khR[l] = emb_r @ Wk_t[l] + bk[l]
    for (int l = 0; l < LL; l++)
        small4_mm_k<<<RR / 4, 256>>>(emb_r, p_wt + (size_t)(LL + l) * DD * DD,
                                     bk + l * DD, p_khR + (size_t)l * RR * DD);
    // ec = emb_e @ W_e  (no bias) : the one big GEMM
    dim3 gEC(DD / 128, (EE + 127) / 128);
    tgemm_k<0><<<gEC, 256, TG_SMEM>>>(emb_e, msgW + (size_t)2 * DD * DD, p_zero,
                                      p_ec, EE, DD, DD);

    dim3 g512(DD / 128, BB / 128);     // 2048 x 512 outputs
    dim3 gF1 (FFD / 128, BB / 128);

    // hc = h @ W_h + msg_b ; value = leaky(hc[b] + rc[nr] + ec[ne])
    tgemm_k<0><<<g512, 256, TG_SMEM>>>(p_h, msgW, msgb, p_hc, BB, DD, DD);
    value_build_k<<<(MROWS * 128) / 256, 256>>>((const float4*)p_hc, (const float4*)p_rc,
                                                (const float4*)p_ec, nr, ne,
                                                (float4*)p_val);

    for (int l = 0; l < LL; l++) {
        // qh = emb_q @ Wq_t[l] + bq[l]
        tgemm_k<0><<<g512, 256, TG_SMEM>>>(p_q, p_wt + (size_t)l * DD * DD,
                                           bq + l * DD, p_qh, BB, DD, DD);
        // fused attention -> mix [B, 4096]
        attn_fused_k<<<BB, 256>>>(p_qh, p_khR + (size_t)l * RR * DD, nr, masks,
                                  p_val, p_mix);
        // x = mix @ blockdiag(Wv[l]) + bv[l]
        tgemm_k<0><<<g512, 256, TG_SMEM>>>(p_mix, p_wvb + (size_t)l * 4096 * 512,
                                           bv + l * DD, p_x, BB, DD, 4096);
        addln_k<<<BB, 256>>>(p_h, p_x, l1g + l * DD, l1b + l * DD);

        tgemm_k<1><<<gF1, 256, TG_SMEM>>>(p_h, fW1 + (size_t)l * DD * FFD,
                                          fb1 + l * FFD, p_ff, BB, FFD, DD);
        tgemm_k<0><<<g512, 256, TG_SMEM>>>(p_ff, fW2 + (size_t)l * FFD * DD,
                                           fb2 + l * DD, p_x, BB, DD, FFD);
        addln_k<<<BB, 256>>>(p_h, p_x, l2g + l * DD, l2b + l * DD);

        if (l < LL - 1) {
            tgemm_k<0><<<g512, 256, TG_SMEM>>>(p_h, msgW, msgb, p_hc, BB, DD, DD);
            value_build_k<<<(MROWS * 128) / 256, 256>>>((const float4*)p_hc,
                                                        (const float4*)p_rc,
                                                        (const float4*)p_ec, nr, ne,
                                                        (float4*)p_val);
        }
    }

    out_copy_k<<<(BB * DD) / 256, 256>>>(p_h, out);
}

// round 4
// speedup vs baseline: 1.4498x; 1.4498x over previous
#include <cuda_runtime.h>
#include <math.h>
#include <stdint.h>

#define BB   2048
#define NN   64
#define DD   512
#define HH   8
#define HDIM 64
#define LL   3
#define FFD  2048
#define EE   100000
#define RR   400

// ---------------- scratch (allocation-free: __device__ globals) ----------------
__device__ float g_h   [BB*DD];
__device__ float g_q   [BB*DD];
__device__ float g_hc  [BB*DD];
__device__ float g_qh  [BB*3*DD];       // [b][l*512+j]
__device__ float g_x   [BB*DD];
__device__ float g_ff  [BB*FFD];
__device__ float g_mix [BB*HH*DD];      // [b][h*512+d]
__device__ float g_ec  [EE*DD];         // 205 MB
__device__ float g_rk  [RR*4*DD];       // [r][ rc(512) | khR l0 | l1 | l2 ]
__device__ float g_rkw [DD*4*DD];       // combined B for rk GEMM [k][2048]
__device__ float g_rkb [4*DD];
__device__ float g_qw  [DD*3*DD];       // combined B for q GEMM [k][1536]
__device__ float g_qb  [3*DD];
__device__ float g_wvb [LL*HH*DD*DD];   // block-diag Wv: [l][4096][512]
__device__ float g_zero[DD];            // zero bias (never written)

// ---------------- helpers ----------------
__device__ __forceinline__ float to_tf32(float x) {
    uint32_t u;
    asm("cvt.rna.tf32.f32 %0, %1;" : "=r"(u) : "f"(x));
    return __uint_as_float(u);
}

__device__ __forceinline__ void mma_tf32(float c[4], const float a[4], const float b[2]) {
    uint32_t a0 = __float_as_uint(a[0]), a1 = __float_as_uint(a[1]);
    uint32_t a2 = __float_as_uint(a[2]), a3 = __float_as_uint(a[3]);
    uint32_t b0 = __float_as_uint(b[0]), b1 = __float_as_uint(b[1]);
    asm volatile(
        "mma.sync.aligned.m16n8k8.row.col.f32.tf32.tf32.f32 "
        "{%0,%1,%2,%3}, {%4,%5,%6,%7}, {%8,%9}, {%0,%1,%2,%3};\n"
        : "+f"(c[0]), "+f"(c[1]), "+f"(c[2]), "+f"(c[3])
        : "r"(a0), "r"(a1), "r"(a2), "r"(a3), "r"(b0), "r"(b1));
}

// ---------------- weight prep ----------------
// combined rk weights: B[k][0:512] = W_r (msgW rows 512..1023), B[k][512+l*512+jj] = Wk[l]
__global__ void prep_rkw_k(const float* __restrict__ msgW, const float* __restrict__ Wk,
                           const float* __restrict__ bk,
                           float* __restrict__ w, float* __restrict__ bias) {
    int idx = blockIdx.x * blockDim.x + threadIdx.x;  // 512*2048
    int k = idx >> 11, j = idx & 2047;
    float v;
    if (j < 512) {
        v = msgW[(size_t)(512 + k) * 512 + j];
    } else {
        int m = j - 512;
        int l = m >> 9, jj = m & 511;
        v = Wk[(((size_t)(l * 8 + (jj >> 6)) * 512) + k) * 64 + (jj & 63)];
    }
    w[idx] = v;
    if (k == 0)
        bias[j] = (j < 512) ? 0.f : bk[((j - 512) >> 9) * 512 + ((j - 512) & 511)];
}

// combined q weights: B[k][l*512+jj] = Wq[l,jj>>6,k,jj&63]
__global__ void prep_qw_k(const float* __restrict__ Wq, const float* __restrict__ bq,
                          float* __restrict__ w, float* __restrict__ bias) {
    int idx = blockIdx.x * blockDim.x + threadIdx.x;  // 512*1536
    int k = idx / 1536, j = idx - k * 1536;
    int l = j >> 9, jj = j & 511;
    w[idx] = Wq[(((size_t)(l * 8 + (jj >> 6)) * 512) + k) * 64 + (jj & 63)];
    if (k == 0) bias[j] = bq[l * 512 + jj];
}

// block-diagonal Wv: wvb[l][h*512+d][h*64+e] = Wv[l,h,d,e], else 0
__global__ void prep_wvb_k(const float* __restrict__ Wv, float* __restrict__ wvb) {
    int idx = blockIdx.x * blockDim.x + threadIdx.x;  // LL*4096*512
    int j    = idx & 511;
    int rest = idx >> 9;
    int row  = rest & 4095;
    int l    = rest >> 12;
    int hr = row >> 9, d = row & 511;
    int hj = j >> 6,  e = j & 63;
    float v = 0.f;
    if (hr == hj) v = Wv[(((size_t)l * HH + hr) * DD + d) * HDIM + e];
    wvb[idx] = v;
}

// ---------------- gathers ----------------
__global__ void gather_hq_k(const int* __restrict__ e1, const int* __restrict__ qi,
                            const float* __restrict__ emb_e, const float* __restrict__ emb_r,
                            float* __restrict__ h, float* __restrict__ q,
                            float* __restrict__ out, int writeQ) {
    int idx = blockIdx.x * blockDim.x + threadIdx.x;   // BB*DD
    int b = idx >> 9;
    h[idx] = emb_e[(size_t)e1[b] * DD + (idx & 511)];
    float qv = emb_r[(size_t)qi[b] * DD + (idx & 511)];
    q[idx] = qv;
    if (writeQ) out[BB * DD + idx] = qv;
}

// ---------------- TF32 split tensor-core GEMM ----------------
// C[M,Ncol] = act(A @ B + bias). BM=BN=128, BK=32, 256 threads, 8 warps (2x4).
// x = hi + lo tf32 split; accumulate hi*hi + hi*lo + lo*hi.
// K-window: per-block k range = [blockIdx.x * kbegStride, + Keff).
// EPI 0: none, 1: relu
#define SLABF 4224
#define TG_SMEM (2 * 4 * SLABF * 4)   // 135168 bytes

template<int EPI>
__global__ void __launch_bounds__(256, 1)
tgemm_k(const float* __restrict__ A, const float* __restrict__ Bm,
        const float* __restrict__ bias, float* __restrict__ C,
        int M, int Ncol, int K, int kbegStride, int Keff) {
    extern __shared__ float smem[];
    int tid  = threadIdx.x;
    int lane = tid & 31, wid = tid >> 5;
    int warp_m = wid & 1, warp_n = wid >> 1;
    int g = lane >> 2, t4 = lane & 3;
    int bm = blockIdx.y * 128, bn = blockIdx.x * 128;
    int kbeg = blockIdx.x * kbegStride;

    int a_kq = tid & 7, a_r0 = tid >> 3;
    int b_n4 = tid & 31, b_k0 = tid >> 5;

    float c[4][4][4];
    #pragma unroll
    for (int i = 0; i < 4; i++)
        #pragma unroll
        for (int j = 0; j < 4; j++)
            #pragma unroll
            for (int r = 0; r < 4; r++) c[i][j][r] = 0.f;

    float4 regA[4], regB[4];

    auto loadG = [&](int k0) {
        int k = k0 + a_kq * 4;
        #pragma unroll
        for (int i = 0; i < 4; i++) {
            int row = bm + a_r0 + i * 32;
            if (row >= M) row = M - 1;
            regA[i] = *(const float4*)(A + (size_t)row * K + k);
        }
        #pragma unroll
        for (int i = 0; i < 4; i++) {
            int kr = k0 + b_k0 + i * 8;
            regB[i] = *(const float4*)(Bm + (size_t)kr * Ncol + bn + b_n4 * 4);
        }
    };

    auto storeS = [&](int st) {
        float* aH = smem + st * 4 * SLABF;
        float* aL = aH + SLABF;
        float* bH = aH + 2 * SLABF;
        float* bL = aH + 3 * SLABF;
        #pragma unroll
        for (int i = 0; i < 4; i++) {
            float v[4] = {regA[i].x, regA[i].y, regA[i].z, regA[i].w};
            #pragma unroll
            for (int j = 0; j < 4; j++) {
                float hi = to_tf32(v[j]);
                float lo = to_tf32(v[j] - hi);
                int off = (a_kq * 4 + j) * 132 + a_r0 + i * 32;
                aH[off] = hi;
                aL[off] = lo;
            }
        }
        #pragma unroll
        for (int i = 0; i < 4; i++) {
            float v[4] = {regB[i].x, regB[i].y, regB[i].z, regB[i].w};
            float h0 = to_tf32(v[0]), h1 = to_tf32(v[1]);
            float h2 = to_tf32(v[2]), h3 = to_tf32(v[3]);
            float4 hv = make_float4(h0, h1, h2, h3);
            float4 lv = make_float4(to_tf32(v[0] - h0), to_tf32(v[1] - h1),
                                    to_tf32(v[2] - h2), to_tf32(v[3] - h3));
            int off = (b_k0 + i * 8) * 132 + b_n4 * 4;
            *(float4*)&bH[off] = hv;
            *(float4*)&bL[off] = lv;
        }
    };

    auto compute = [&](int st) {
        float* aH = smem + st * 4 * SLABF;
        float* aL = aH + SLABF;
        float* bH = aH + 2 * SLABF;
        float* bL = aH + 3 * SLABF;
        #pragma unroll
        for (int ks = 0; ks < 4; ks++) {
            int kb = ks * 8;
            float ah[4][4], al[4][4];
            #pragma unroll
            for (int mt = 0; mt < 4; mt++) {
                int rm = warp_m * 64 + mt * 16 + g;
                int o0 = (kb + t4) * 132 + rm;
                int o1 = (kb + t4 + 4) * 132 + rm;
                ah[mt][0] = aH[o0];     ah[mt][1] = aH[o0 + 8];
                ah[mt][2] = aH[o1];     ah[mt][3] = aH[o1 + 8];
                al[mt][0] = aL[o0];     al[mt][1] = aL[o0 + 8];
                al[mt][2] = aL[o1];     al[mt][3] = aL[o1 + 8];
            }
            float bh[4][2], bl[4][2];
            #pragma unroll
            for (int nt = 0; nt < 4; nt++) {
                int cn = warp_n * 32 + nt * 8 + g;
                bh[nt][0] = bH[(kb + t4) * 132 + cn];
                bh[nt][1] = bH[(kb + t4 + 4) * 132 + cn];
                bl[nt][0] = bL[(kb + t4) * 132 + cn];
                bl[nt][1] = bL[(kb + t4 + 4) * 132 + cn];
            }
            #pragma unroll
            for (int mt = 0; mt < 4; mt++)
                #pragma unroll
                for (int nt = 0; nt < 4; nt++) {
                    mma_tf32(c[mt][nt], ah[mt], bh[nt]);
                    mma_tf32(c[mt][nt], ah[mt], bl[nt]);
                    mma_tf32(c[mt][nt], al[mt], bh[nt]);
                }
        }
    };

    int nslab = Keff >> 5;
    loadG(kbeg);
    storeS(0);
    __syncthreads();
    int cur = 0;
    for (int s = 0; s < nslab; s++) {
        if (s + 1 < nslab) loadG(kbeg + (s + 1) * 32);
        compute(cur);
        if (s + 1 < nslab) storeS(cur ^ 1);
        __syncthreads();
        cur ^= 1;
    }

    #pragma unroll
    for (int mt = 0; mt < 4; mt++) {
        int r0 = bm + warp_m * 64 + mt * 16 + g;
        #pragma unroll
        for (int nt = 0; nt < 4; nt++) {
            int cc = bn + warp_n * 32 + nt * 8 + 2 * t4;
            float bi0 = bias[cc], bi1 = bias[cc + 1];
            float v0 = c[mt][nt][0] + bi0, v1 = c[mt][nt][1] + bi1;
            float v2 = c[mt][nt][2] + bi0, v3 = c[mt][nt][3] + bi1;
            if (EPI == 1) {
                v0 = fmaxf(v0, 0.f); v1 = fmaxf(v1, 0.f);
                v2 = fmaxf(v2, 0.f); v3 = fmaxf(v3, 0.f);
            }
            if (r0 < M)
                *(float2*)(C + (size_t)r0 * Ncol + cc) = make_float2(v0, v1);
            if (r0 + 8 < M)
                *(float2*)(C + (size_t)(r0 + 8) * Ncol + cc) = make_float2(v2, v3);
        }
    }
}

// ---------------- fused attention (value built on the fly) ----------------
// one block per batch b, 256 threads (8 warps = 8 heads)
// value[n][d] = leaky(hc[b][d] + rk[nr[n]][d] + ec[ne[n]][d])
__global__ void __launch_bounds__(256)
attn_fused_k(const float* __restrict__ qh,    // + b*1536 row, already offset by l*512
             const float* __restrict__ rk, int kh_off,
             const int* __restrict__ nr, const int* __restrict__ ne,
             const float* __restrict__ masks, const float* __restrict__ ec,
             const float* __restrict__ hc, float* __restrict__ mix) {
    __shared__ float qs[512];
    __shared__ float hcs[512];
    __shared__ float attn_s[8][64];
    __shared__ int   nr_s[64];
    __shared__ int   ne_s[64];
    __shared__ float msk_s[64];
    __shared__ float vs[16][516];
    int b = blockIdx.x, tid = threadIdx.x;
    int lane = tid & 31, h = tid >> 5;

    qs[tid]        = qh[(size_t)b * 1536 + tid];
    qs[tid + 256]  = qh[(size_t)b * 1536 + tid + 256];
    hcs[tid]       = hc[(size_t)b * 512 + tid];
    hcs[tid + 256] = hc[(size_t)b * 512 + tid + 256];
    if (tid < 64) {
        nr_s[tid]  = nr[b * 64 + tid];
        ne_s[tid]  = ne[b * 64 + tid];
        msk_s[tid] = masks[b * 64 + tid];
    }
    __syncthreads();

    // scores
    float sc[2];
    #pragma unroll
    for (int half = 0; half < 2; half++) {
        int n = lane + 32 * half;
        const float4* kr = (const float4*)(rk + (size_t)nr_s[n] * 2048 + kh_off + h * 64);
        float v = 0.f;
        #pragma unroll
        for (int i = 0; i < 16; i++) {
            float4 k4 = kr[i];
            v += qs[h * 64 + 4 * i]     * k4.x;
            v += qs[h * 64 + 4 * i + 1] * k4.y;
            v += qs[h * 64 + 4 * i + 2] * k4.z;
            v += qs[h * 64 + 4 * i + 3] * k4.w;
        }
        sc[half] = v * 0.125f - 1e31f * (1.f - msk_s[n]);
    }
    float mx = fmaxf(sc[0], sc[1]);
    #pragma unroll
    for (int o = 16; o; o >>= 1) mx = fmaxf(mx, __shfl_xor_sync(0xffffffffu, mx, o));
    float e0 = expf(sc[0] - mx), e1 = expf(sc[1] - mx);
    float sm = e0 + e1;
    #pragma unroll
    for (int o = 16; o; o >>= 1) sm += __shfl_xor_sync(0xffffffffu, sm, o);
    float inv = 1.f / sm;
    attn_s[h][lane]      = e0 * inv;
    attn_s[h][lane + 32] = e1 * inv;

    // mix[h][d] = sum_n attn[h][n] * value[n][d]
    float acc[16];
    #pragma unroll
    for (int i = 0; i < 16; i++) acc[i] = 0.f;

    int rr = tid >> 4, cc = tid & 15;
    const float4* hc4 = (const float4*)hcs;
    for (int c = 0; c < 4; c++) {
        __syncthreads();
        int n = c * 16 + rr;
        const float4* ecr = (const float4*)(ec + (size_t)ne_s[n] * 512);
        const float4* rcr = (const float4*)(rk + (size_t)nr_s[n] * 2048);
        #pragma unroll
        for (int i = 0; i < 8; i++) {
            int d4 = cc + i * 16;
            float4 e4 = ecr[d4], r4 = rcr[d4], h4 = hc4[d4];
            float4 v;
            v.x = e4.x + r4.x + h4.x;  v.y = e4.y + r4.y + h4.y;
            v.z = e4.z + r4.z + h4.z;  v.w = e4.w + r4.w + h4.w;
            v.x = (v.x > 0.f) ? v.x : 0.01f * v.x;
            v.y = (v.y > 0.f) ? v.y : 0.01f * v.y;
            v.z = (v.z > 0.f) ? v.z : 0.01f * v.z;
            v.w = (v.w > 0.f) ? v.w : 0.01f * v.w;
            *(float4*)&vs[rr][d4 * 4] = v;
        }
        __syncthreads();
        #pragma unroll
        for (int n2 = 0; n2 < 16; n2++) {
            float a = attn_s[h][c * 16 + n2];
            #pragma unroll
            for (int i = 0; i < 16; i++) acc[i] += a * vs[n2][lane + 32 * i];
        }
    }

    float* mo = mix + (size_t)b * 4096 + h * 512;
    #pragma unroll
    for (int i = 0; i < 16; i++) mo[lane + 32 * i] = acc[i];
}

// ---------------- residual add + layernorm (biased var, eps=1e-5) ----------------
__global__ void addln_k(float* __restrict__ h, const float* __restrict__ x,
                        const float* __restrict__ g, const float* __restrict__ be) {
    __shared__ float red[8];
    int b = blockIdx.x, t = threadIdx.x;  // 256
    size_t base = (size_t)b * DD;
    float v0 = h[base + t]       + x[base + t];
    float v1 = h[base + t + 256] + x[base + t + 256];
    float s = v0 + v1;
    #pragma unroll
    for (int o = 16; o; o >>= 1) s += __shfl_xor_sync(0xffffffffu, s, o);
    if ((t & 31) == 0) red[t >> 5] = s;
    __syncthreads();
    float mean = 0.f;
    #pragma unroll
    for (int i = 0; i < 8; i++) mean += red[i];
    mean *= (1.0f / DD);
    __syncthreads();
    float d0 = v0 - mean, d1 = v1 - mean;
    float vs = d0 * d0 + d1 * d1;
    #pragma unroll
    for (int o = 16; o; o >>= 1) vs += __shfl_xor_sync(0xffffffffu, vs, o);
    if ((t & 31) == 0) red[t >> 5] = vs;
    __syncthreads();
    float var = 0.f;
    #pragma unroll
    for (int i = 0; i < 8; i++) var += red[i];
    var *= (1.0f / DD);
    float inv = rsqrtf(var + 1e-5f);
    h[base + t]       = d0 * inv * g[t]       + be[t];
    h[base + t + 256] = d1 * inv * g[t + 256] + be[t + 256];
}

__global__ void out_copy_k(const float* __restrict__ h, float* __restrict__ out) {
    int idx = blockIdx.x * blockDim.x + threadIdx.x;
    out[idx] = h[idx];
}

// ---------------- launch ----------------
extern "C" void kernel_launch(void* const* d_in, const int* in_sizes, int n_in,
                              void* d_out, int out_size) {
    const int*   e1    = (const int*)  d_in[0];
    const int*   qi    = (const int*)  d_in[1];
    const int*   nr    = (const int*)  d_in[2];
    const int*   ne    = (const int*)  d_in[3];
    const float* masks = (const float*)d_in[4];
    const float* emb_e = (const float*)d_in[5];
    const float* emb_r = (const float*)d_in[6];
    const float* msgW  = (const float*)d_in[7];
    const float* msgb  = (const float*)d_in[8];
    const float* Wq    = (const float*)d_in[9];
    const float* bq    = (const float*)d_in[10];
    const float* Wk    = (const float*)d_in[11];
    const float* bk    = (const float*)d_in[12];
    const float* Wv    = (const float*)d_in[13];
    const float* bv    = (const float*)d_in[14];
    const float* fW1   = (const float*)d_in[15];
    const float* fb1   = (const float*)d_in[16];
    const float* fW2   = (const float*)d_in[17];
    const float* fb2   = (const float*)d_in[18];
    const float* l1g   = (const float*)d_in[19];
    const float* l1b   = (const float*)d_in[20];
    const float* l2g   = (const float*)d_in[21];
    const float* l2b   = (const float*)d_in[22];
    float* out = (float*)d_out;

    float *p_h, *p_q, *p_hc, *p_qh, *p_x, *p_ff, *p_mix, *p_ec, *p_rk, *p_rkw, *p_rkb,
          *p_qw, *p_qb, *p_wvb, *p_zero;
    cudaGetSymbolAddress((void**)&p_h,   g_h);
    cudaGetSymbolAddress((void**)&p_q,   g_q);
    cudaGetSymbolAddress((void**)&p_hc,  g_hc);
    cudaGetSymbolAddress((void**)&p_qh,  g_qh);
    cudaGetSymbolAddress((void**)&p_x,   g_x);
    cudaGetSymbolAddress((void**)&p_ff,  g_ff);
    cudaGetSymbolAddress((void**)&p_mix, g_mix);
    cudaGetSymbolAddress((void**)&p_ec,  g_ec);
    cudaGetSymbolAddress((void**)&p_rk,  g_rk);
    cudaGetSymbolAddress((void**)&p_rkw, g_rkw);
    cudaGetSymbolAddress((void**)&p_rkb, g_rkb);
    cudaGetSymbolAddress((void**)&p_qw,  g_qw);
    cudaGetSymbolAddress((void**)&p_qb,  g_qb);
    cudaGetSymbolAddress((void**)&p_wvb, g_wvb);
    cudaGetSymbolAddress((void**)&p_zero,g_zero);

    cudaFuncSetAttribute(tgemm_k<0>, cudaFuncAttributeMaxDynamicSharedMemorySize, TG_SMEM);
    cudaFuncSetAttribute(tgemm_k<1>, cudaFuncAttributeMaxDynamicSharedMemorySize, TG_SMEM);

    int writeQ = (out_size >= 2 * BB * DD) ? 1 : 0;

    // ---- prep (launch order keeps ec GEMM at skip index 5 for ncu) ----
    prep_rkw_k<<<(512 * 2048) / 256, 256>>>(msgW, Wk, bk, p_rkw, p_rkb);          // 0
    prep_qw_k<<<(512 * 1536) / 256, 256>>>(Wq, bq, p_qw, p_qb);                   // 1
    prep_wvb_k<<<(LL * 4096 * 512) / 256, 256>>>(Wv, p_wvb);                      // 2
    gather_hq_k<<<(BB * DD) / 256, 256>>>(e1, qi, emb_e, emb_r, p_h, p_q, out, writeQ); // 3

    // rk = emb_r @ [W_r | Wk0 | Wk1 | Wk2] (+ [0|bk])
    dim3 gRK(2048 / 128, (RR + 127) / 128);
    tgemm_k<0><<<gRK, 256, TG_SMEM>>>(emb_r, p_rkw, p_rkb, p_rk,
                                      RR, 2048, 512, 0, 512);                     // 4
    // ec = emb_e @ W_e
    dim3 gEC(DD / 128, (EE + 127) / 128);
    tgemm_k<0><<<gEC, 256, TG_SMEM>>>(emb_e, msgW + (size_t)1024 * 512, p_zero,
                                      p_ec, EE, 512, 512, 0, 512);                // 5  <- profiled
    // qh_all = emb_q @ [Wq0|Wq1|Wq2] + bq
    dim3 gQH(1536 / 128, BB / 128);
    tgemm_k<0><<<gQH, 256, TG_SMEM>>>(p_q, p_qw, p_qb, p_qh,
                                      BB, 1536, 512, 0, 512);                     // 6

    dim3 g512(DD / 128, BB / 128);
    dim3 gF1 (FFD / 128, BB / 128);

    // hc = h @ W_h + msg_b  (h-part of msg_enc; r/e parts folded into attn)
    tgemm_k<0><<<g512, 256, TG_SMEM>>>(p_h, msgW, msgb, p_hc, BB, 512, 512, 0, 512); // 7

    for (int l = 0; l < LL; l++) {
        attn_fused_k<<<BB, 256>>>(p_qh + l * 512, p_rk, 512 * (l + 1),
                                  nr, ne, masks, p_ec, p_hc, p_mix);
        // x = mix @ blockdiag(Wv[l]) + bv[l]   (K-window: 1024 per N-tile)
        tgemm_k<0><<<g512, 256, TG_SMEM>>>(p_mix, p_wvb + (size_t)l * 4096 * 512,
                                           bv + l * DD, p_x, BB, 512, 4096, 1024, 1024);
        addln_k<<<BB, 256>>>(p_h, p_x, l1g + l * DD, l1b + l * DD);

        tgemm_k<1><<<gF1, 256, TG_SMEM>>>(p_h, fW1 + (size_t)l * DD * FFD,
                                          fb1 + l * FFD, p_ff, BB, FFD, 512, 0, 512);
        tgemm_k<0><<<g512, 256, TG_SMEM>>>(p_ff, fW2 + (size_t)l * FFD * DD,
                                           fb2 + l * DD, p_x, BB, 512, FFD, 0, FFD);
        addln_k<<<BB, 256>>>(p_h, p_x, l2g + l * DD, l2b + l * DD);

        if (l < LL - 1)
            tgemm_k<0><<<g512, 256, TG_SMEM>>>(p_h, msgW, msgb, p_hc,
                                               BB, 512, 512, 0, 512);
    }

    out_copy_k<<<(BB * DD) / 256, 256>>>(p_h, out);
}

// round 5
// speedup vs baseline: 2.0003x; 1.3797x over previous
#include <cuda_runtime.h>
#include <cuda_bf16.h>
#include <math.h>
#include <stdint.h>

#define BB   2048
#define NN   64
#define DD   512
#define HH   8
#define HDIM 64
#define LL   3
#define FFD  2048
#define EE   100000
#define RR   400

// ---------------- scratch (allocation-free: __device__ globals) ----------------
__device__ float g_h   [BB*DD];
__device__ float g_q   [BB*DD];
__device__ float g_hc  [BB*DD];
__device__ float g_qh  [BB*3*DD];       // [b][l*512+j]
__device__ float g_x   [BB*DD];
__device__ float g_ff  [BB*FFD];
__device__ float g_mix [BB*HH*DD];      // [b][h*512+d]
__device__ float g_ec  [EE*DD];         // 205 MB
__device__ float g_rk  [RR*4*DD];       // [r][ rc(512) | khR l0 | l1 | l2 ]
__device__ float g_rkw [DD*4*DD];       // combined B for rk GEMM [k][2048]
__device__ float g_rkb [4*DD];
__device__ float g_qw  [DD*3*DD];       // combined B for q GEMM [k][1536]
__device__ float g_qb  [3*DD];
__device__ float g_wvb [LL*HH*DD*DD];   // block-diag Wv: [l][4096][512]
__device__ float g_zero[DD];            // zero bias (never written)

// ---------------- helpers ----------------
__device__ __forceinline__ void mma_bf16(float c[4], const uint32_t a[4],
                                         const uint32_t b[2]) {
    asm volatile(
        "mma.sync.aligned.m16n8k16.row.col.f32.bf16.bf16.f32 "
        "{%0,%1,%2,%3}, {%4,%5,%6,%7}, {%8,%9}, {%0,%1,%2,%3};\n"
        : "+f"(c[0]), "+f"(c[1]), "+f"(c[2]), "+f"(c[3])
        : "r"(a[0]), "r"(a[1]), "r"(a[2]), "r"(a[3]), "r"(b[0]), "r"(b[1]));
}

// split x = hi + lo (both bf16); returns raw ushorts
__device__ __forceinline__ void bsplit(float x, uint32_t& h, uint32_t& l) {
    __nv_bfloat16 hb = __float2bfloat16_rn(x);
    float r = x - __bfloat162float(hb);
    __nv_bfloat16 lb = __float2bfloat16_rn(r);
    h = (uint32_t)__bfloat16_as_ushort(hb);
    l = (uint32_t)__bfloat16_as_ushort(lb);
}

// ---------------- weight prep ----------------
__global__ void prep_rkw_k(const float* __restrict__ msgW, const float* __restrict__ Wk,
                           const float* __restrict__ bk,
                           float* __restrict__ w, float* __restrict__ bias) {
    int idx = blockIdx.x * blockDim.x + threadIdx.x;  // 512*2048
    int k = idx >> 11, j = idx & 2047;
    float v;
    if (j < 512) {
        v = msgW[(size_t)(512 + k) * 512 + j];
    } else {
        int m = j - 512;
        int l = m >> 9, jj = m & 511;
        v = Wk[(((size_t)(l * 8 + (jj >> 6)) * 512) + k) * 64 + (jj & 63)];
    }
    w[idx] = v;
    if (k == 0)
        bias[j] = (j < 512) ? 0.f : bk[((j - 512) >> 9) * 512 + ((j - 512) & 511)];
}

__global__ void prep_qw_k(const float* __restrict__ Wq, const float* __restrict__ bq,
                          float* __restrict__ w, float* __restrict__ bias) {
    int idx = blockIdx.x * blockDim.x + threadIdx.x;  // 512*1536
    int k = idx / 1536, j = idx - k * 1536;
    int l = j >> 9, jj = j & 511;
    w[idx] = Wq[(((size_t)(l * 8 + (jj >> 6)) * 512) + k) * 64 + (jj & 63)];
    if (k == 0) bias[j] = bq[l * 512 + jj];
}

__global__ void prep_wvb_k(const float* __restrict__ Wv, float* __restrict__ wvb) {
    int idx = blockIdx.x * blockDim.x + threadIdx.x;  // LL*4096*512
    int j    = idx & 511;
    int rest = idx >> 9;
    int row  = rest & 4095;
    int l    = rest >> 12;
    int hr = row >> 9, d = row & 511;
    int hj = j >> 6,  e = j & 63;
    float v = 0.f;
    if (hr == hj) v = Wv[(((size_t)l * HH + hr) * DD + d) * HDIM + e];
    wvb[idx] = v;
}

// ---------------- gathers ----------------
__global__ void gather_hq_k(const int* __restrict__ e1, const int* __restrict__ qi,
                            const float* __restrict__ emb_e, const float* __restrict__ emb_r,
                            float* __restrict__ h, float* __restrict__ q,
                            float* __restrict__ out, int writeQ) {
    int idx = blockIdx.x * blockDim.x + threadIdx.x;   // BB*DD
    int b = idx >> 9;
    h[idx] = emb_e[(size_t)e1[b] * DD + (idx & 511)];
    float qv = emb_r[(size_t)qi[b] * DD + (idx & 511)];
    q[idx] = qv;
    if (writeQ) out[BB * DD + idx] = qv;
}

// ---------------- bf16-split tensor-core GEMM ----------------
// C[M,Ncol] = act(A @ B + bias). BM=BN=128, BK=32, 256 threads, 8 warps (2x4).
// x = hi + lo (bf16); products hi*hi + hi*lo + lo*hi via mma.m16n8k16.
// smem planes (uint32 words): per stage AH|AL|BH|BL, each 16 k2-rows * stride 136.
// K-window: per-block k range = [blockIdx.x * kbegStride, + Keff).
// EPI 0: none, 1: relu
#define PL   2176            // 16*136 words per plane
#define STGW (4*PL)          // words per stage
#define TG_SMEM (2 * STGW * 4)   // 69632 bytes

template<int EPI>
__global__ void __launch_bounds__(256, 2)
tgemm_k(const float* __restrict__ A, const float* __restrict__ Bm,
        const float* __restrict__ bias, float* __restrict__ C,
        int M, int Ncol, int K, int kbegStride, int Keff) {
    extern __shared__ uint32_t s32[];
    int tid  = threadIdx.x;
    int lane = tid & 31, wid = tid >> 5;
    int warp_m = wid & 1, warp_n = wid >> 1;
    int g = lane >> 2, t4 = lane & 3;
    int bm = blockIdx.y * 128, bn = blockIdx.x * 128;
    int kbeg = blockIdx.x * kbegStride;

    int a_kq = tid & 7, a_r0 = tid >> 3;   // A: k-quad, row base (4 rows stride 32)
    int b_n4 = tid & 31, b_kp = tid >> 5;  // B: col quad, k-pair base (pairs kp, kp+8)

    float c[4][4][4];
    #pragma unroll
    for (int i = 0; i < 4; i++)
        #pragma unroll
        for (int j = 0; j < 4; j++)
            #pragma unroll
            for (int r = 0; r < 4; r++) c[i][j][r] = 0.f;

    float4 regA[4], regB[4];

    auto loadG = [&](int k0) {
        int k = k0 + a_kq * 4;
        #pragma unroll
        for (int i = 0; i < 4; i++) {
            int row = bm + a_r0 + i * 32;
            if (row >= M) row = M - 1;
            regA[i] = *(const float4*)(A + (size_t)row * K + k);
        }
        #pragma unroll
        for (int pi = 0; pi < 2; pi++) {
            int kr = k0 + 2 * b_kp + 16 * pi;
            regB[pi * 2]     = *(const float4*)(Bm + (size_t)kr * Ncol + bn + b_n4 * 4);
            regB[pi * 2 + 1] = *(const float4*)(Bm + (size_t)(kr + 1) * Ncol + bn + b_n4 * 4);
        }
    };

    auto storeS = [&](int st) {
        uint32_t* aH = s32 + st * STGW;
        uint32_t* aL = aH + PL;
        uint32_t* bH = aH + 2 * PL;
        uint32_t* bL = aH + 3 * PL;
        #pragma unroll
        for (int i = 0; i < 4; i++) {
            float v[4] = {regA[i].x, regA[i].y, regA[i].z, regA[i].w};
            #pragma unroll
            for (int j = 0; j < 2; j++) {
                uint32_t h0, l0, h1, l1;
                bsplit(v[2 * j],     h0, l0);
                bsplit(v[2 * j + 1], h1, l1);
                int off = (a_kq * 2 + j) * 136 + a_r0 + i * 32;
                aH[off] = h0 | (h1 << 16);
                aL[off] = l0 | (l1 << 16);
            }
        }
        #pragma unroll
        for (int pi = 0; pi < 2; pi++) {
            int p = b_kp + pi * 8;
            float e[4] = {regB[pi*2].x, regB[pi*2].y, regB[pi*2].z, regB[pi*2].w};
            float o[4] = {regB[pi*2+1].x, regB[pi*2+1].y, regB[pi*2+1].z, regB[pi*2+1].w};
            uint32_t hv[4], lv[4];
            #pragma unroll
            for (int q2 = 0; q2 < 4; q2++) {
                uint32_t he, le, ho, lo;
                bsplit(e[q2], he, le);
                bsplit(o[q2], ho, lo);
                hv[q2] = he | (ho << 16);
                lv[q2] = le | (lo << 16);
            }
            int off = p * 136 + b_n4 * 4;
            *(uint4*)&bH[off] = make_uint4(hv[0], hv[1], hv[2], hv[3]);
            *(uint4*)&bL[off] = make_uint4(lv[0], lv[1], lv[2], lv[3]);
        }
    };

    auto compute = [&](int st) {
        const uint32_t* aH = s32 + st * STGW;
        const uint32_t* aL = aH + PL;
        const uint32_t* bH = aH + 2 * PL;
        const uint32_t* bL = aH + 3 * PL;
        #pragma unroll
        for (int kc = 0; kc < 2; kc++) {
            int k2b = kc * 8;
            uint32_t bhf[4][2], blf[4][2];
            #pragma unroll
            for (int nt = 0; nt < 4; nt++) {
                int cn = warp_n * 32 + nt * 8 + g;
                int u0 = (k2b + t4) * 136 + cn;
                int u1 = (k2b + t4 + 4) * 136 + cn;
                bhf[nt][0] = bH[u0]; bhf[nt][1] = bH[u1];
                blf[nt][0] = bL[u0]; blf[nt][1] = bL[u1];
            }
            #pragma unroll
            for (int mt = 0; mt < 4; mt++) {
                int rm = warp_m * 64 + mt * 16 + g;
                int o0 = (k2b + t4) * 136 + rm;
                int o1 = (k2b + t4 + 4) * 136 + rm;
                uint32_t ah[4] = {aH[o0], aH[o0 + 8], aH[o1], aH[o1 + 8]};
                uint32_t al[4] = {aL[o0], aL[o0 + 8], aL[o1], aL[o1 + 8]};
                #pragma unroll
                for (int nt = 0; nt < 4; nt++) {
                    mma_bf16(c[mt][nt], ah, bhf[nt]);
                    mma_bf16(c[mt][nt], ah, blf[nt]);
                    mma_bf16(c[mt][nt], al, bhf[nt]);
                }
            }
        }
    };

    int nslab = Keff >> 5;
    loadG(kbeg);
    storeS(0);
    __syncthreads();
    int cur = 0;
    for (int s = 0; s < nslab; s++) {
        if (s + 1 < nslab) loadG(kbeg + (s + 1) * 32);
        compute(cur);
        if (s + 1 < nslab) storeS(cur ^ 1);
        __syncthreads();
        cur ^= 1;
    }

    #pragma unroll
    for (int mt = 0; mt < 4; mt++) {
        int r0 = bm + warp_m * 64 + mt * 16 + g;
        #pragma unroll
        for (int nt = 0; nt < 4; nt++) {
            int cc = bn + warp_n * 32 + nt * 8 + 2 * t4;
            float bi0 = bias[cc], bi1 = bias[cc + 1];
            float v0 = c[mt][nt][0] + bi0, v1 = c[mt][nt][1] + bi1;
            float v2 = c[mt][nt][2] + bi0, v3 = c[mt][nt][3] + bi1;
            if (EPI == 1) {
                v0 = fmaxf(v0, 0.f); v1 = fmaxf(v1, 0.f);
                v2 = fmaxf(v2, 0.f); v3 = fmaxf(v3, 0.f);
            }
            if (r0 < M)
                *(float2*)(C + (size_t)r0 * Ncol + cc) = make_float2(v0, v1);
            if (r0 + 8 < M)
                *(float2*)(C + (size_t)(r0 + 8) * Ncol + cc) = make_float2(v2, v3);
        }
    }
}

// ---------------- fused attention (value built on the fly) ----------------
__global__ void __launch_bounds__(256)
attn_fused_k(const float* __restrict__ qh,
             const float* __restrict__ rk, int kh_off,
             const int* __restrict__ nr, const int* __restrict__ ne,
             const float* __restrict__ masks, const float* __restrict__ ec,
             const float* __restrict__ hc, float* __restrict__ mix) {
    __shared__ float qs[512];
    __shared__ float hcs[512];
    __shared__ float attn_s[8][64];
    __shared__ int   nr_s[64];
    __shared__ int   ne_s[64];
    __shared__ float msk_s[64];
    __shared__ float vs[16][516];
    int b = blockIdx.x, tid = threadIdx.x;
    int lane = tid & 31, h = tid >> 5;

    qs[tid]        = qh[(size_t)b * 1536 + tid];
    qs[tid + 256]  = qh[(size_t)b * 1536 + tid + 256];
    hcs[tid]       = hc[(size_t)b * 512 + tid];
    hcs[tid + 256] = hc[(size_t)b * 512 + tid + 256];
    if (tid < 64) {
        nr_s[tid]  = nr[b * 64 + tid];
        ne_s[tid]  = ne[b * 64 + tid];
        msk_s[tid] = masks[b * 64 + tid];
    }
    __syncthreads();

    float sc[2];
    #pragma unroll
    for (int half = 0; half < 2; half++) {
        int n = lane + 32 * half;
        const float4* kr = (const float4*)(rk + (size_t)nr_s[n] * 2048 + kh_off + h * 64);
        float v = 0.f;
        #pragma unroll
        for (int i = 0; i < 16; i++) {
            float4 k4 = kr[i];
            v += qs[h * 64 + 4 * i]     * k4.x;
            v += qs[h * 64 + 4 * i + 1] * k4.y;
            v += qs[h * 64 + 4 * i + 2] * k4.z;
            v += qs[h * 64 + 4 * i + 3] * k4.w;
        }
        sc[half] = v * 0.125f - 1e31f * (1.f - msk_s[n]);
    }
    float mx = fmaxf(sc[0], sc[1]);
    #pragma unroll
    for (int o = 16; o; o >>= 1) mx = fmaxf(mx, __shfl_xor_sync(0xffffffffu, mx, o));
    float e0 = expf(sc[0] - mx), e1 = expf(sc[1] - mx);
    float sm = e0 + e1;
    #pragma unroll
    for (int o = 16; o; o >>= 1) sm += __shfl_xor_sync(0xffffffffu, sm, o);
    float inv = 1.f / sm;
    attn_s[h][lane]      = e0 * inv;
    attn_s[h][lane + 32] = e1 * inv;

    float acc[16];
    #pragma unroll
    for (int i = 0; i < 16; i++) acc[i] = 0.f;

    int rr = tid >> 4, cc = tid & 15;
    const float4* hc4 = (const float4*)hcs;
    for (int c = 0; c < 4; c++) {
        __syncthreads();
        int n = c * 16 + rr;
        const float4* ecr = (const float4*)(ec + (size_t)ne_s[n] * 512);
        const float4* rcr = (const float4*)(rk + (size_t)nr_s[n] * 2048);
        #pragma unroll
        for (int i = 0; i < 8; i++) {
            int d4 = cc + i * 16;
            float4 e4 = ecr[d4], r4 = rcr[d4], h4 = hc4[d4];
            float4 v;
            v.x = e4.x + r4.x + h4.x;  v.y = e4.y + r4.y + h4.y;
            v.z = e4.z + r4.z + h4.z;  v.w = e4.w + r4.w + h4.w;
            v.x = (v.x > 0.f) ? v.x : 0.01f * v.x;
            v.y = (v.y > 0.f) ? v.y : 0.01f * v.y;
            v.z = (v.z > 0.f) ? v.z : 0.01f * v.z;
            v.w = (v.w > 0.f) ? v.w : 0.01f * v.w;
            *(float4*)&vs[rr][d4 * 4] = v;
        }
        __syncthreads();
        #pragma unroll
        for (int n2 = 0; n2 < 16; n2++) {
            float a = attn_s[h][c * 16 + n2];
            #pragma unroll
            for (int i = 0; i < 16; i++) acc[i] += a * vs[n2][lane + 32 * i];
        }
    }

    float* mo = mix + (size_t)b * 4096 + h * 512;
    #pragma unroll
    for (int i = 0; i < 16; i++) mo[lane + 32 * i] = acc[i];
}

// ---------------- residual add + layernorm (biased var, eps=1e-5) ----------------
__global__ void addln_k(float* __restrict__ h, const float* __restrict__ x,
                        const float* __restrict__ g, const float* __restrict__ be) {
    __shared__ float red[8];
    int b = blockIdx.x, t = threadIdx.x;  // 256
    size_t base = (size_t)b * DD;
    float v0 = h[base + t]       + x[base + t];
    float v1 = h[base + t + 256] + x[base + t + 256];
    float s = v0 + v1;
    #pragma unroll
    for (int o = 16; o; o >>= 1) s += __shfl_xor_sync(0xffffffffu, s, o);
    if ((t & 31) == 0) red[t >> 5] = s;
    __syncthreads();
    float mean = 0.f;
    #pragma unroll
    for (int i = 0; i < 8; i++) mean += red[i];
    mean *= (1.0f / DD);
    __syncthreads();
    float d0 = v0 - mean, d1 = v1 - mean;
    float vs = d0 * d0 + d1 * d1;
    #pragma unroll
    for (int o = 16; o; o >>= 1) vs += __shfl_xor_sync(0xffffffffu, vs, o);
    if ((t & 31) == 0) red[t >> 5] = vs;
    __syncthreads();
    float var = 0.f;
    #pragma unroll
    for (int i = 0; i < 8; i++) var += red[i];
    var *= (1.0f / DD);
    float inv = rsqrtf(var + 1e-5f);
    h[base + t]       = d0 * inv * g[t]       + be[t];
    h[base + t + 256] = d1 * inv * g[t + 256] + be[t + 256];
}

__global__ void out_copy_k(const float* __restrict__ h, float* __restrict__ out) {
    int idx = blockIdx.x * blockDim.x + threadIdx.x;
    out[idx] = h[idx];
}

// ---------------- launch ----------------
extern "C" void kernel_launch(void* const* d_in, const int* in_sizes, int n_in,
                              void* d_out, int out_size) {
    const int*   e1    = (const int*)  d_in[0];
    const int*   qi    = (const int*)  d_in[1];
    const int*   nr    = (const int*)  d_in[2];
    const int*   ne    = (const int*)  d_in[3];
    const float* masks = (const float*)d_in[4];
    const float* emb_e = (const float*)d_in[5];
    const float* emb_r = (const float*)d_in[6];
    const float* msgW  = (const float*)d_in[7];
    const float* msgb  = (const float*)d_in[8];
    const float* Wq    = (const float*)d_in[9];
    const float* bq    = (const float*)d_in[10];
    const float* Wk    = (const float*)d_in[11];
    const float* bk    = (const float*)d_in[12];
    const float* Wv    = (const float*)d_in[13];
    const float* bv    = (const float*)d_in[14];
    const float* fW1   = (const float*)d_in[15];
    const float* fb1   = (const float*)d_in[16];
    const float* fW2   = (const float*)d_in[17];
    const float* fb2   = (const float*)d_in[18];
    const float* l1g   = (const float*)d_in[19];
    const float* l1b   = (const float*)d_in[20];
    const float* l2g   = (const float*)d_in[21];
    const float* l2b   = (const float*)d_in[22];
    float* out = (float*)d_out;

    float *p_h, *p_q, *p_hc, *p_qh, *p_x, *p_ff, *p_mix, *p_ec, *p_rk, *p_rkw, *p_rkb,
          *p_qw, *p_qb, *p_wvb, *p_zero;
    cudaGetSymbolAddress((void**)&p_h,   g_h);
    cudaGetSymbolAddress((void**)&p_q,   g_q);
    cudaGetSymbolAddress((void**)&p_hc,  g_hc);
    cudaGetSymbolAddress((void**)&p_qh,  g_qh);
    cudaGetSymbolAddress((void**)&p_x,   g_x);
    cudaGetSymbolAddress((void**)&p_ff,  g_ff);
    cudaGetSymbolAddress((void**)&p_mix, g_mix);
    cudaGetSymbolAddress((void**)&p_ec,  g_ec);
    cudaGetSymbolAddress((void**)&p_rk,  g_rk);
    cudaGetSymbolAddress((void**)&p_rkw, g_rkw);
    cudaGetSymbolAddress((void**)&p_rkb, g_rkb);
    cudaGetSymbolAddress((void**)&p_qw,  g_qw);
    cudaGetSymbolAddress((void**)&p_qb,  g_qb);
    cudaGetSymbolAddress((void**)&p_wvb, g_wvb);
    cudaGetSymbolAddress((void**)&p_zero,g_zero);

    cudaFuncSetAttribute(tgemm_k<0>, cudaFuncAttributeMaxDynamicSharedMemorySize, TG_SMEM);
    cudaFuncSetAttribute(tgemm_k<1>, cudaFuncAttributeMaxDynamicSharedMemorySize, TG_SMEM);

    int writeQ = (out_size >= 2 * BB * DD) ? 1 : 0;

    // ---- prep (ec GEMM at my-idx 3 == ncu global idx 5) ----
    prep_rkw_k<<<(512 * 2048) / 256, 256>>>(msgW, Wk, bk, p_rkw, p_rkb);          // 0
    prep_qw_k<<<(512 * 1536) / 256, 256>>>(Wq, bq, p_qw, p_qb);                   // 1
    prep_wvb_k<<<(LL * 4096 * 512) / 256, 256>>>(Wv, p_wvb);                      // 2

    // ec = emb_e @ W_e  (the big one; independent of gathers)
    dim3 gEC(DD / 128, (EE + 127) / 128);
    tgemm_k<0><<<gEC, 256, TG_SMEM>>>(emb_e, msgW + (size_t)1024 * 512, p_zero,
                                      p_ec, EE, 512, 512, 0, 512);                // 3 <- profiled
    gather_hq_k<<<(BB * DD) / 256, 256>>>(e1, qi, emb_e, emb_r, p_h, p_q, out, writeQ); // 4
    // rk = emb_r @ [W_r | Wk0 | Wk1 | Wk2] (+ [0|bk])
    dim3 gRK(2048 / 128, (RR + 127) / 128);
    tgemm_k<0><<<gRK, 256, TG_SMEM>>>(emb_r, p_rkw, p_rkb, p_rk,
                                      RR, 2048, 512, 0, 512);                     // 5
    // qh_all = emb_q @ [Wq0|Wq1|Wq2] + bq
    dim3 gQH(1536 / 128, BB / 128);
    tgemm_k<0><<<gQH, 256, TG_SMEM>>>(p_q, p_qw, p_qb, p_qh,
                                      BB, 1536, 512, 0, 512);                     // 6

    dim3 g512(DD / 128, BB / 128);
    dim3 gF1 (FFD / 128, BB / 128);

    // hc = h @ W_h + msg_b
    tgemm_k<0><<<g512, 256, TG_SMEM>>>(p_h, msgW, msgb, p_hc, BB, 512, 512, 0, 512); // 7

    for (int l = 0; l < LL; l++) {
        attn_fused_k<<<BB, 256>>>(p_qh + l * 512, p_rk, 512 * (l + 1),
                                  nr, ne, masks, p_ec, p_hc, p_mix);
        tgemm_k<0><<<g512, 256, TG_SMEM>>>(p_mix, p_wvb + (size_t)l * 4096 * 512,
                                           bv + l * DD, p_x, BB, 512, 4096, 1024, 1024);
        addln_k<<<BB, 256>>>(p_h, p_x, l1g + l * DD, l1b + l * DD);

        tgemm_k<1><<<gF1, 256, TG_SMEM>>>(p_h, fW1 + (size_t)l * DD * FFD,
                                          fb1 + l * FFD, p_ff, BB, FFD, 512, 0, 512);
        tgemm_k<0><<<g512, 256, TG_SMEM>>>(p_ff, fW2 + (size_t)l * FFD * DD,
                                           fb2 + l * DD, p_x, BB, 512, FFD, 0, FFD);
        addln_k<<<BB, 256>>>(p_h, p_x, l2g + l * DD, l2b + l * DD);

        if (l < LL - 1)
            tgemm_k<0><<<g512, 256, TG_SMEM>>>(p_h, msgW, msgb, p_hc,
                                               BB, 512, 512, 0, 512);
    }

    out_copy_k<<<(BB * DD) / 256, 256>>>(p_h, out);
}